// round 15
// baseline (speedup 1.0000x reference)
#include <cuda_runtime.h>
#include <math.h>

#define HH 1024
#define WW 1024
#define NPIX (HH * WW)
#define N_ITERS 100

// fused-tile geometry: 32x8 own (step-2) pixels per 256-thread block
#define SXW 36      // sx: input x tile, halo 2   (12 rows x 36 cols)
#define SXH 12
#define SYW 34      // sy: step-1 tile, halo 1    (10 rows x 34 cols)
#define SYH 10

// ---------------- device scratch (statically allocated, ~36 MB) ----------------
__device__ uint4  g_wq[NPIX];       // 8x unorm16 weights per pixel (16B)
__device__ float  g_Y[NPIX];        // luminance plane
__device__ float2 g_x0[NPIX];       // ping
__device__ float2 g_x1[NPIX];       // pong

__device__ __forceinline__ float luma(float r, float g, float b) {
    return (0.3f * r + 0.59f * g + 0.11f * b) * (1.0f / 255.0f);
}

// ---------------- prep: setup + weights fused (one pass) ----------------
__global__ void prep_kernel(const float* __restrict__ gray,
                            const float* __restrict__ app) {
    int pix = blockIdx.x * blockDim.x + threadIdx.x;
    if (pix >= NPIX) return;
    int i = pix / WW, j = pix % WW;

    float g0 = gray[3*pix+0], g1 = gray[3*pix+1], g2 = gray[3*pix+2];
    float a0 = app [3*pix+0], a1 = app [3*pix+1], a2 = app [3*pix+2];

    const float inv255 = 1.0f / 255.0f;
    float diff = (fabsf(g0-a0) + fabsf(g1-a1) + fabsf(g2-a2)) * inv255;
    bool colored = diff > 0.01f;

    float Y = luma(g0, g1, g2);

    float ya = luma(a0, a1, a2);
    float r  = a0 * inv255;
    float bl = a2 * inv255;
    float I = 0.74f*(r - ya) - 0.27f*(bl - ya);
    float Q = 0.48f*(r - ya) + 0.41f*(bl - ya);

    g_Y[pix]  = Y;
    g_x0[pix] = colored ? make_float2(I, Q) : make_float2(0.0f, 0.0f);

    const int di[8] = {-1,-1,-1, 0, 0, 1, 1, 1};
    const int dj[8] = {-1, 0, 1,-1, 1,-1, 0, 1};

    float nbr[8], valid[8];
    #pragma unroll
    for (int k = 0; k < 8; k++) {
        int ii = i + di[k], jj = j + dj[k];
        bool in = (ii >= 0) & (ii < HH) & (jj >= 0) & (jj < WW);
        valid[k] = in ? 1.0f : 0.0f;
        if (in) {
            int np = (ii * WW + jj) * 3;
            nbr[k] = luma(gray[np], gray[np+1], gray[np+2]);
        } else {
            nbr[k] = 0.0f;
        }
    }

    float count = 1.0f, s = Y;
    #pragma unroll
    for (int k = 0; k < 8; k++) { count += valid[k]; s += nbr[k] * valid[k]; }
    float mean = s / count;

    float var = (Y - mean) * (Y - mean);
    #pragma unroll
    for (int k = 0; k < 8; k++) {
        float d = nbr[k] - mean;
        var += d * d * valid[k];
    }
    var /= count;
    float vs = fmaxf(0.6f * var, 2e-6f);
    float inv_vs = 1.0f / vs;

    float w[8], wsum = 0.0f;
    #pragma unroll
    for (int k = 0; k < 8; k++) {
        float d = nbr[k] - Y;
        w[k] = expf(-d * d * inv_vs) * valid[k];
        wsum += w[k];
    }
    // colored pixels: all weights 0 (the all-zero pattern encodes "colored")
    float scale = (colored ? 0.0f : 1.0f) / wsum * 65535.0f;

    unsigned int u[8];
    #pragma unroll
    for (int k = 0; k < 8; k++) u[k] = (unsigned int)rintf(w[k] * scale);

    uint4 q;
    q.x = u[0] | (u[1] << 16);
    q.y = u[2] | (u[3] << 16);
    q.z = u[4] | (u[5] << 16);
    q.w = u[6] | (u[7] << 16);
    g_wq[pix] = q;
}

__device__ __forceinline__ void unpack_w(uint4 q, float* w, float& c) {
    const float S = 1.0f / 65535.0f;
    w[0] = (float)(q.x & 0xFFFFu) * S;  w[1] = (float)(q.x >> 16) * S;
    w[2] = (float)(q.y & 0xFFFFu) * S;  w[3] = (float)(q.y >> 16) * S;
    w[4] = (float)(q.z & 0xFFFFu) * S;  w[5] = (float)(q.z >> 16) * S;
    w[6] = (float)(q.w & 0xFFFFu) * S;  w[7] = (float)(q.w >> 16) * S;
    c = ((q.x | q.y | q.z | q.w) == 0u) ? 1.0f : 0.0f;
}

// 9-tap weighted sum at (r+1, c+1) of a [.][COLS] smem tile (identical
// expression order to the standalone kernel -> bitwise-identical results)
template <int COLS>
__device__ __forceinline__ float2 tap9(const float2 (*s)[COLS], int r, int c,
                                       const float* w, float cc) {
    float2 ctr = s[r+1][c+1];
    float ax = cc * ctr.x, ay = cc * ctr.y;
    float2 t;
    t = s[r  ][c  ]; ax = fmaf(w[0], t.x, ax); ay = fmaf(w[0], t.y, ay);
    t = s[r  ][c+1]; ax = fmaf(w[1], t.x, ax); ay = fmaf(w[1], t.y, ay);
    t = s[r  ][c+2]; ax = fmaf(w[2], t.x, ax); ay = fmaf(w[2], t.y, ay);
    t = s[r+1][c  ]; ax = fmaf(w[3], t.x, ax); ay = fmaf(w[3], t.y, ay);
    t = s[r+1][c+2]; ax = fmaf(w[4], t.x, ax); ay = fmaf(w[4], t.y, ay);
    t = s[r+2][c  ]; ax = fmaf(w[5], t.x, ax); ay = fmaf(w[5], t.y, ay);
    t = s[r+2][c+1]; ax = fmaf(w[6], t.x, ax); ay = fmaf(w[6], t.y, ay);
    t = s[r+2][c+2]; ax = fmaf(w[7], t.x, ax); ay = fmaf(w[7], t.y, ay);
    return make_float2(ax, ay);
}

// fused double-step body: loads sx (36x12), computes sy (34x10) cooperatively,
// returns this thread's step-2 value. Clamped out-of-image slots hold garbage
// that is always annihilated by exactly-zero border weights.
__device__ __forceinline__ float2 fuse2_body(const float2* __restrict__ xin,
                                             float2 (*sx)[SXW],
                                             float2 (*sy)[SYW],
                                             int bi0, int bj0, int tid) {
    // ---- load input tile 36x12 (432 elems, 1.69/thread) ----
    #pragma unroll
    for (int idx = tid; idx < SXH * SXW; idx += 256) {
        int r = idx / SXW, c = idx % SXW;
        int gi = min(max(bi0 - 2 + r, 0), HH - 1);
        int gj = min(max(bj0 - 2 + c, 0), WW - 1);
        sx[r][c] = xin[gi * WW + gj];
    }
    __syncthreads();

    // ---- step 1: 34x10 region (340 elems, uniform cooperative loop) ----
    #pragma unroll
    for (int idx = tid; idx < SYH * SYW; idx += 256) {
        int r = idx / SYW, c = idx % SYW;
        int gi = min(max(bi0 - 1 + r, 0), HH - 1);
        int gj = min(max(bj0 - 1 + c, 0), WW - 1);
        uint4 q = g_wq[gi * WW + gj];
        float w[8], cc;
        unpack_w(q, w, cc);
        sy[r][c] = tap9<SXW>(sx, r, c, w, cc);   // sx(r..r+2, c..c+2)
    }
    __syncthreads();

    // ---- step 2: own pixel ----
    int ty = tid >> 5, tx = tid & 31;
    int i = bi0 + ty, j = bj0 + tx;
    uint4 q = g_wq[i * WW + j];
    float w[8], cc;
    unpack_w(q, w, cc);
    return tap9<SYW>(sy, ty, tx, w, cc);
}

// ---------------- fused 2-step iteration, direction specialized ----------------
template <bool SRC_IS_X0>
__global__ void __launch_bounds__(256)
fuse2_kernel_t() {
    __shared__ float2 sx[SXH][SXW];
    __shared__ float2 sy[SYH][SYW];
    int tid = threadIdx.y * 32 + threadIdx.x;
    int bi0 = blockIdx.y * 8;
    int bj0 = blockIdx.x * 32;

    const float2* __restrict__ xin  = SRC_IS_X0 ? g_x0 : g_x1;
    float2*       __restrict__ xout = SRC_IS_X0 ? g_x1 : g_x0;

    float2 v = fuse2_body(xin, sx, sy, bi0, bj0, tid);
    xout[(bi0 + (tid >> 5)) * WW + bj0 + (tid & 31)] = v;
}

// ---------------- last fused double-step + YIQ->RGB ----------------
__global__ void __launch_bounds__(256)
fuse2_final_kernel(float* __restrict__ out) {
    __shared__ float2 sx[SXH][SXW];
    __shared__ float2 sy[SYH][SYW];
    int tid = threadIdx.y * 32 + threadIdx.x;
    int bi0 = blockIdx.y * 8;
    int bj0 = blockIdx.x * 32;

    // 49 fused kernels done (98 steps): k=48 (even, read x0) wrote x1 -> read x1
    float2 v = fuse2_body(g_x1, sx, sy, bi0, bj0, tid);

    int i = bi0 + (tid >> 5), j = bj0 + (tid & 31);
    int pix = i * WW + j;
    float y = g_Y[pix];
    float I = v.x, Q = v.y;
    float r = y + 0.9468822170900693f  * I + 0.6235565819861433f * Q;
    float g = y - 0.27478764629897834f * I - 0.6356910791873801f * Q;
    float b = y - 1.1085450346420322f  * I + 1.7090069284064666f * Q;
    int o = 3 * pix;
    out[o+0] = fminf(fmaxf(r, 0.0f), 1.0f) * 255.0f;
    out[o+1] = fminf(fmaxf(g, 0.0f), 1.0f) * 255.0f;
    out[o+2] = fminf(fmaxf(b, 0.0f), 1.0f) * 255.0f;
}

extern "C" void kernel_launch(void* const* d_in, const int* in_sizes, int n_in,
                              void* d_out, int out_size) {
    const float* gray = (const float*)d_in[0];
    const float* app  = (const float*)d_in[1];
    float* out = (float*)d_out;

    int threads = 256;
    int blocks1d = (NPIX + threads - 1) / threads;

    prep_kernel<<<blocks1d, threads>>>(gray, app);

    dim3 blk(32, 8);
    dim3 grd(WW / 32, HH / 8);
    // 49 fused double-steps (98 iterations), alternating ping-pong
    for (int k = 0; k < N_ITERS / 2 - 1; k++) {
        if ((k & 1) == 0) fuse2_kernel_t<true ><<<grd, blk>>>();
        else              fuse2_kernel_t<false><<<grd, blk>>>();
    }
    // 50th fused double-step (iterations 99+100) + RGB conversion
    fuse2_final_kernel<<<grd, blk>>>(out);
}